// round 7
// baseline (speedup 1.0000x reference)
#include <cuda_runtime.h>
#include <cuda_fp16.h>
#include <cstdint>

#define BB   256
#define TT   256
#define KTOK 128
#define HH   512
#define G4H  2048
#define DD   128

#define NCTA 128
#define NTHR 256

// smem layout
#define RED_OFF   0u
#define RED_PITCH 160u                      // 40 words/row (conflict = 2-wf floor)
#define RED_BUF   (128u * RED_PITCH)        // 20480 per kq buffer
#define BG_OFF    0u                        // init-only staging, overlays RED
#define BG_PITCH  80u
#define BO_OFF    81920u                    // 2 x 8192 (vk-ordered out cols)
#define BO_BUF    8192u
#define BO_PITCH  16u
#define XG_OFF    98304u
#define SMEM_BYTES 98560u

__device__ __half    g_h[2][BB * HH];
__device__ unsigned  g_cnt[2 * 8 * 32];     // [half][group] counters, 128B apart

__global__ void reset_kernel() { if (threadIdx.x < 512) g_cnt[threadIdx.x] = 0u; }

__device__ __forceinline__ uint32_t smem_u32(const void* p) {
    uint32_t a;
    asm("{ .reg .u64 t; cvta.to.shared.u64 t, %1; cvt.u32.u64 %0, t; }" : "=r"(a) : "l"(p));
    return a;
}
__device__ __forceinline__ float tanha(float x) {
    float r; asm("tanh.approx.f32 %0, %1;" : "=f"(r) : "f"(x)); return r;
}
__device__ __forceinline__ float sigm(float x) { return fmaf(0.5f, tanha(0.5f * x), 0.5f); }

__device__ __forceinline__ void ldsm_x4t(uint32_t* r, uint32_t addr) {
    asm volatile("ldmatrix.sync.aligned.m8n8.x4.trans.shared.b16 {%0,%1,%2,%3}, [%4];"
        : "=r"(r[0]), "=r"(r[1]), "=r"(r[2]), "=r"(r[3]) : "r"(addr));
}
__device__ __forceinline__ void ldsm_x2t(uint32_t* r, uint32_t addr) {
    asm volatile("ldmatrix.sync.aligned.m8n8.x2.trans.shared.b16 {%0,%1}, [%2];"
        : "=r"(r[0]), "=r"(r[1]) : "r"(addr));
}
__device__ __forceinline__ void mma16816(float* d, uint32_t a0, uint32_t a1, uint32_t a2,
                                         uint32_t a3, const uint32_t* b) {
    asm volatile("mma.sync.aligned.m16n8k16.row.col.f32.f16.f16.f32 "
        "{%0,%1,%2,%3}, {%4,%5,%6,%7}, {%8,%9}, {%0,%1,%2,%3};"
        : "+f"(d[0]), "+f"(d[1]), "+f"(d[2]), "+f"(d[3])
        : "r"(a0), "r"(a1), "r"(a2), "r"(a3), "r"(b[0]), "r"(b[1]));
}

// k permutation within 32-blocks (same as R6): direct LDG.128 -> mma A fragments
__device__ __forceinline__ int vk_to_ak(int vk) {
    int kfl = (vk >> 4) & 1, pair = (vk >> 3) & 1, qc = (vk >> 1) & 3, elem = vk & 1;
    return (vk & ~31) + 8 * qc + kfl * 4 + pair * 2 + elem;
}
__device__ __forceinline__ int ak_to_vk(int ak) {
    int qc = (ak >> 3) & 3, j = ak & 7;
    return (ak & ~31) + (j >> 2) * 16 + ((j >> 1) & 1) * 8 + qc * 2 + (j & 1);
}

__global__ void __launch_bounds__(NTHR, 1) lstm_mma_kernel(
    const float* __restrict__ z,     const float* __restrict__ Wz,
    const float* __restrict__ bz,    const float* __restrict__ token,
    const float* __restrict__ Wi,    const float* __restrict__ Wh,
    const float* __restrict__ bh,    const float* __restrict__ Wout,
    const float* __restrict__ bout,  float* __restrict__ out)
{
    extern __shared__ char smem[];
    const uint32_t sb = smem_u32(smem);

    const int tid  = threadIdx.x;
    const int lane = tid & 31;
    const int w    = tid >> 5;            // warp 0..7
    const int kq   = w & 3;               // k-range: kq*128
    const int mq   = w >> 2;              // row-range: mq*64
    const int mh   = blockIdx.x & 1;      // batch half (sync domain)
    const int jg   = blockIdx.x >> 1;     // unit group 0..63 (8 units)
    const int m0   = mh * 128;
    const int j0   = jg * 8;
    const int grp  = jg & 7;              // barrier group (8 CTAs each)

    const int qr   = lane >> 2;
    const int qc   = lane & 3;

    const uint32_t bgLane = sb + BG_OFF + (uint32_t)(lane & 15) * BG_PITCH
                          + (uint32_t)(lane >> 4) * 16u;
    const uint32_t boLane = sb + BO_OFF + (uint32_t)(lane & 15) * BO_PITCH;

    float* sxg = (float*)(smem + XG_OFF);
    volatile unsigned* cnts = &g_cnt[mh * 8 * 32];

    // ---------------- one-time init ----------------
    for (int i = tid; i < 1024; i += NTHR) ((uint4*)(smem + BO_OFF))[i] = make_uint4(0, 0, 0, 0);

    // stage Wh slice -> fp16 smem, VIRTUAL k order (init only; region reused as RED)
    for (int idx = tid; idx < 512 * 32; idx += NTHR) {
        int vk = idx >> 5, n = idx & 31;
        int ak = vk_to_ak(vk);
        float v = __ldg(&Wh[(size_t)ak * G4H + (n >> 3) * HH + j0 + (n & 7)]);
        *(__half*)(smem + BG_OFF + (uint32_t)vk * BG_PITCH + (uint32_t)n * 2u) = __float2half_rn(v);
    }
    if (tid < 32) {
        int col = (tid >> 3) * HH + j0 + (tid & 7);
        float s = bh[col];
        #pragma unroll 4
        for (int k = 0; k < KTOK; ++k)
            s = fmaf(token[k], __ldg(&Wi[(size_t)k * G4H + col]), s);
        sxg[tid] = s;
    }
    {   // h0 = relu(z @ Wz + bz)
        const int r  = tid >> 1;
        const int ub = (tid & 1) * 4;
        float a[4];
        #pragma unroll
        for (int q = 0; q < 4; ++q) a[q] = bz[j0 + ub + q];
        const float* zr = z + (size_t)(m0 + r) * KTOK;
        #pragma unroll 4
        for (int k = 0; k < KTOK; ++k) {
            float zv = __ldg(zr + k);
            float4 w4 = __ldg((const float4*)&Wz[(size_t)k * HH + j0 + ub]);
            a[0] = fmaf(zv, w4.x, a[0]); a[1] = fmaf(zv, w4.y, a[1]);
            a[2] = fmaf(zv, w4.z, a[2]); a[3] = fmaf(zv, w4.w, a[3]);
        }
        __half2* hp = (__half2*)&g_h[0][(size_t)(m0 + r) * KTOK * 0 + (size_t)(m0 + r) * HH + j0 + ub];
        hp[0] = __floats2half2_rn(fmaxf(a[0], 0.f), fmaxf(a[1], 0.f));
        hp[1] = __floats2half2_rn(fmaxf(a[2], 0.f), fmaxf(a[3], 0.f));
    }
    __syncthreads();

    // B-gate fragments -> registers (held for entire sequence)
    uint32_t bg[8][8];
    #pragma unroll
    for (int ks = 0; ks < 8; ++ks) {
        uint32_t row = (uint32_t)(kq * 128 + ks * 16);
        ldsm_x4t(&bg[ks][0], bgLane + row * BG_PITCH);
        ldsm_x4t(&bg[ks][4], bgLane + row * BG_PITCH + 32u);
    }
    __syncthreads();   // BG region now dead -> reused as RED buffers

    // initial barrier (ep = 1)
    unsigned ep = 1;
    if (tid == 0) {
        __threadfence();
        asm volatile("red.global.add.u32 [%0], %1;" :: "l"((unsigned*)&cnts[grp * 32]), "r"(1u) : "memory");
    }
    if (tid < 8) { while (cnts[tid * 32] < ep * 8u) {} }
    __syncthreads();
    if (tid == 0) __threadfence();
    __syncthreads();
    ++ep;

    float c4[4] = {0.f, 0.f, 0.f, 0.f};
    float2 wo0, wo1;

    // ---------------- sequential loop ----------------
    #pragma unroll 1
    for (int t = 0; t <= TT; ++t) {
        const __half* hsrc = g_h[t & 1];
        const int te = t - 1;

        // A base: rows mq*64 + f*16 + qr (+8), k-range kq*128, lane chunk 8*qc
        const __half* aBase = hsrc + (size_t)(m0 + mq * 64 + qr) * HH + kq * 128 + 8 * qc;

        // B-out fragments for this step (8 ldsm, k-rows of this warp's range)
        uint32_t bo[8][2];
        {
            const uint32_t boSel = boLane + (uint32_t)(t & 1) * BO_BUF;
            #pragma unroll
            for (int ks = 0; ks < 8; ++ks)
                ldsm_x2t(bo[ks], boSel + (uint32_t)(kq * 128 + ks * 16) * BO_PITCH);
        }

        // prefetch Wout_t for next iteration
        if (t < TT) {
            const float* Wo = Wout + (size_t)t * HH * DD + jg * 2;
            wo0 = __ldcg((const float2*)(Wo + (size_t)(tid * 2) * DD));
            wo1 = __ldcg((const float2*)(Wo + (size_t)(tid * 2 + 1) * DD));
        }

        float acc[4][5][4];
        #pragma unroll
        for (int f = 0; f < 4; ++f)
            #pragma unroll
            for (int n = 0; n < 5; ++n)
                #pragma unroll
                for (int e = 0; e < 4; ++e) acc[f][n][e] = 0.f;

        // 16 flat blocks: fb = f*4 + b; 4-deep LDG ring
        uint4 ra[4], rb[4];
        #pragma unroll
        for (int p = 0; p < 4; ++p) {
            ra[p] = __ldcg((const uint4*)(aBase + p * 32));
            rb[p] = __ldcg((const uint4*)(aBase + 8 * HH + p * 32));
        }
        #pragma unroll
        for (int fb = 0; fb < 16; ++fb) {
            const int f = fb >> 2, b = fb & 3;
            const int slot = fb & 3;
            const uint4 va = ra[slot], vb = rb[slot];
            if (fb + 4 < 16) {
                const int nf = (fb + 4) >> 2, nb = (fb + 4) & 3;
                const __half* p = aBase + (size_t)nf * 16 * HH + nb * 32;
                ra[slot] = __ldcg((const uint4*)p);
                rb[slot] = __ldcg((const uint4*)(p + 8 * HH));
            }
            #pragma unroll
            for (int kfl = 0; kfl < 2; ++kfl) {
                const int ks = b * 2 + kfl;
                const uint32_t a0 = kfl ? va.z : va.x;
                const uint32_t a1 = kfl ? vb.z : vb.x;
                const uint32_t a2 = kfl ? va.w : va.y;
                const uint32_t a3 = kfl ? vb.w : vb.y;
                mma16816(acc[f][0], a0, a1, a2, a3, &bg[ks][0]);
                mma16816(acc[f][1], a0, a1, a2, a3, &bg[ks][2]);
                mma16816(acc[f][2], a0, a1, a2, a3, &bg[ks][4]);
                mma16816(acc[f][3], a0, a1, a2, a3, &bg[ks][6]);
                mma16816(acc[f][4], a0, a1, a2, a3, bo[ks]);
            }
        }

        // ---- write kq-partials to reduction buffers ----
        {
            char* buf = smem + RED_OFF + (uint32_t)kq * RED_BUF;
            #pragma unroll
            for (int f = 0; f < 4; ++f) {
                const uint32_t r0 = (uint32_t)(mq * 64 + f * 16 + qr);
                #pragma unroll
                for (int g = 0; g < 5; ++g) {
                    const uint32_t col = (uint32_t)(g * 8 + 2 * qc);
                    *(float2*)(buf + r0 * RED_PITCH + col * 4u)        = make_float2(acc[f][g][0], acc[f][g][1]);
                    *(float2*)(buf + (r0 + 8) * RED_PITCH + col * 4u)  = make_float2(acc[f][g][2], acc[f][g][3]);
                }
            }
        }
        __syncthreads();

        // ---- owner warp w: rows w*16+qr, +8; units 2qc, 2qc+1 ----
        float2 os[2];
        {
            const uint32_t rowA = (uint32_t)(w * 16 + qr);
            float hv[2][2];
            #pragma unroll
            for (int r = 0; r < 2; ++r) {
                const uint32_t ro = (rowA + 8u * r) * RED_PITCH;
                float2 gs[4];
                #pragma unroll
                for (int g = 0; g < 4; ++g) {
                    const uint32_t co = ro + (uint32_t)(g * 8 + 2 * qc) * 4u;
                    float2 s = *(const float2*)(smem + RED_OFF + co);
                    #pragma unroll
                    for (int u2 = 1; u2 < 4; ++u2) {
                        float2 v = *(const float2*)(smem + RED_OFF + u2 * RED_BUF + co);
                        s.x += v.x; s.y += v.y;
                    }
                    gs[g] = s;
                }
                if (qc == 0 && t >= 1) {
                    const uint32_t co = ro + 32u * 4u;
                    float2 s = *(const float2*)(smem + RED_OFF + co);
                    #pragma unroll
                    for (int u2 = 1; u2 < 4; ++u2) {
                        float2 v = *(const float2*)(smem + RED_OFF + u2 * RED_BUF + co);
                        s.x += v.x; s.y += v.y;
                    }
                    os[r] = s;
                }
                if (t < TT) {
                    #pragma unroll
                    for (int cc = 0; cc < 2; ++cc) {
                        const int u = 2 * qc + cc;
                        float gv = cc ? gs[0].y : gs[0].x;
                        float fv = cc ? gs[1].y : gs[1].x;
                        float ggv = cc ? gs[2].y : gs[2].x;
                        float ov = cc ? gs[3].y : gs[3].x;
                        float gi = sigm (gv  + sxg[u]);
                        float gf = sigm (fv  + sxg[8 + u]);
                        float gg = tanha(ggv + sxg[16 + u]);
                        float go = sigm (ov  + sxg[24 + u]);
                        float cv = gf * c4[r * 2 + cc] + gi * gg;
                        c4[r * 2 + cc] = cv;
                        hv[r][cc] = go * tanha(cv);
                    }
                }
            }
            if (t < TT) {
                __half* hdst = &g_h[(t + 1) & 1][0];
                __stcg((__half2*)&hdst[(size_t)(m0 + rowA) * HH + j0 + 2 * qc],
                       __floats2half2_rn(hv[0][0], hv[0][1]));
                __stcg((__half2*)&hdst[(size_t)(m0 + rowA + 8) * HH + j0 + 2 * qc],
                       __floats2half2_rn(hv[1][0], hv[1][1]));
            }
        }

        __syncthreads();
        // ---- barrier arrive ----
        if (t < TT && tid == 0) {
            __threadfence();
            asm volatile("red.global.add.u32 [%0], %1;" :: "l"((unsigned*)&cnts[grp * 32]), "r"(1u) : "memory");
        }

        // ---- shadow: out store + next BO staging ----
        if (t >= 1 && qc == 0) {
            const float2 bo2 = *(const float2*)&bout[te * DD + jg * 2];
            const uint32_t rowA = (uint32_t)(w * 16 + qr);
            *(float2*)&out[(size_t)(m0 + rowA) * TT * DD + (size_t)te * DD + jg * 2] =
                make_float2(os[0].x + bo2.x, os[0].y + bo2.y);
            *(float2*)&out[(size_t)(m0 + rowA + 8) * TT * DD + (size_t)te * DD + jg * 2] =
                make_float2(os[1].x + bo2.x, os[1].y + bo2.y);
        }
        if (t < TT) {
            const uint32_t boNext = BO_OFF + (uint32_t)((t + 1) & 1) * BO_BUF;
            __half2 p0 = __floats2half2_rn(wo0.x, wo0.y);
            __half2 p1 = __floats2half2_rn(wo1.x, wo1.y);
            *(uint32_t*)(smem + boNext + (uint32_t)ak_to_vk(tid * 2) * BO_PITCH)     = *(uint32_t*)&p0;
            *(uint32_t*)(smem + boNext + (uint32_t)ak_to_vk(tid * 2 + 1) * BO_PITCH) = *(uint32_t*)&p1;
        }

        // ---- barrier wait ----
        if (t < TT) {
            if (tid < 8) { while (cnts[tid * 32] < ep * 8u) {} }
            __syncthreads();
            if (tid == 0) __threadfence();
            __syncthreads();
            ++ep;
        }
    }
}

extern "C" void kernel_launch(void* const* d_in, const int* in_sizes, int n_in,
                              void* d_out, int out_size) {
    const float* z     = (const float*)d_in[0];
    const float* Wz    = (const float*)d_in[1];
    const float* bz    = (const float*)d_in[2];
    const float* token = (const float*)d_in[3];
    const float* Wi    = (const float*)d_in[4];
    const float* Wh    = (const float*)d_in[5];
    const float* bh    = (const float*)d_in[6];
    const float* Wout  = (const float*)d_in[7];
    const float* bout  = (const float*)d_in[8];
    float* out = (float*)d_out;

    cudaFuncSetAttribute(lstm_mma_kernel, cudaFuncAttributeMaxDynamicSharedMemorySize, SMEM_BYTES);
    reset_kernel<<<1, 512>>>();
    lstm_mma_kernel<<<NCTA, NTHR, SMEM_BYTES>>>(z, Wz, bz, token, Wi, Wh, bh, Wout, bout, out);
}